// round 8
// baseline (speedup 1.0000x reference)
#include <cuda_runtime.h>
#include <math.h>
#include <stdint.h>

// Round 8: legacy HMMA measured at ~FFMA-class rate on GB300 (round 7 was
// neutral), tcgen05 blocked by the harness's compute_103 PTX path. Switch
// the distance GEMM + MLP to packed fp32 FFMA2 (fma.rn.f32x2, base-family
// sm_100+ PTX): 2x fp32 throughput, exact-fp32 numerics (no bf16 split).

#define NB 4
#define NC 64
#define NN 8192
#define NO 128
#define KK 20

// ---------------- scratch (device globals: allocation-free) ----------------
__device__ float g_xt[NB * NN * NC];   // x transposed: [b][n][c]
__device__ float g_ntxxh[NB * NN];     // -0.5 * ||x||^2
__device__ int   g_idx[NB * NN * KK];  // top-K neighbor sets (unsorted)

// ---------------- f32x2 helpers ----------------
__device__ __forceinline__ unsigned long long pk2(float a, float b) {
    unsigned long long r;
    asm("mov.b64 %0, {%1, %2};" : "=l"(r) : "f"(a), "f"(b));
    return r;
}
__device__ __forceinline__ void upk2(float& a, float& b, unsigned long long v) {
    asm("mov.b64 {%0, %1}, %2;" : "=f"(a), "=f"(b) : "l"(v));
}
__device__ __forceinline__ void fma2(unsigned long long& d, unsigned long long a,
                                     unsigned long long b) {
    asm("fma.rn.f32x2 %0, %1, %2, %0;" : "+l"(d) : "l"(a), "l"(b));
}
__device__ __forceinline__ unsigned long long mul2(unsigned long long a,
                                                   unsigned long long b) {
    unsigned long long r;
    asm("mul.rn.f32x2 %0, %1, %2;" : "=l"(r) : "l"(a), "l"(b));
    return r;
}

// ============================================================================
// K1: transpose x[b][c][n] -> xt[b][n][c], and ntxxh = -0.5*sum_c x^2
// ============================================================================
__global__ __launch_bounds__(256) void k_prep(const float* __restrict__ x) {
    __shared__ float t[64 * 65];
    int b = blockIdx.y;
    int n0 = blockIdx.x * 64;
    int tid = threadIdx.x;
    const float* xb = x + (size_t)b * NC * NN;

    for (int i = tid; i < 64 * 64; i += 256) {
        int c = i >> 6, nn = i & 63;
        t[c * 65 + nn] = xb[c * NN + n0 + nn];
    }
    __syncthreads();
    for (int i = tid; i < 64 * 64; i += 256) {
        int nn = i >> 6, c = i & 63;
        g_xt[((size_t)b * NN + n0 + nn) * NC + c] = t[c * 65 + nn];
    }
    if (tid < 64) {
        float s = 0.f;
        #pragma unroll
        for (int c = 0; c < 64; c++) { float v = t[c * 65 + tid]; s += v * v; }
        g_ntxxh[b * NN + n0 + tid] = -0.5f * s;
    }
}

// ============================================================================
// K2: FFMA2 distance GEMM + distributed-register top-20.
// CTA = 64 rows (8 warps x 8 rows), col tiles of 256; 8 cols/lane.
// pd = dot + (-0.5||m||^2)   (monotone in reference key => same set).
// Rows stored pre-duplicated (v,v) so the broadcast operand is load-ready;
// cols load as ulonglong2 (native packed pairs).
// dyn smem (floats): tile[64][260] @0 | row2(float2)[64][65] @16640 | ntxx[256] @24960
// ============================================================================
#define KNN_SMEM (25216 * 4)

__global__ __launch_bounds__(256, 2) void k_knn(const float* __restrict__ x) {
    extern __shared__ float sm[];
    float*  s_tile = sm;                        // [64][260]
    float2* s_row2 = (float2*)(sm + 16640);     // [64][65] (v,v) pairs
    float*  s_ntxx = sm + 24960;                // [256]

    int tid = threadIdx.x, lane = tid & 31, w = tid >> 5;
    int b = blockIdx.y;
    int r0 = blockIdx.x * 64;
    const float* xb = x + (size_t)b * NC * NN;

    // rows, duplicated into both f32x2 halves
    for (int i = tid; i < 64 * 64; i += 256) {
        int r = i & 63, c = i >> 6;
        float v = xb[c * NN + r0 + r];
        s_row2[r * 65 + c] = make_float2(v, v);
    }

    // distributed top-20 state: lane e<20 holds entry e of each of 8 rows
    float val[8], rmin[8]; int idxr[8];
    #pragma unroll
    for (int j = 0; j < 8; j++) {
        val[j] = (lane < KK) ? -INFINITY : INFINITY;
        idxr[j] = 0;
        rmin[j] = -INFINITY;
    }

    for (int m0 = 0; m0 < NN; m0 += 256) {
        __syncthreads();
        for (int i = tid; i < 64 * 64; i += 256) {
            int c = i >> 6, m4 = i & 63;
            float4 v = *(const float4*)&xb[c * NN + m0 + 4 * m4];
            *(float4*)&s_tile[c * 260 + 4 * m4] = v;
        }
        s_ntxx[tid] = g_ntxxh[b * NN + m0 + tid];
        __syncthreads();

        // accumulate: 8 rows x 4 col-pairs per lane (cols 8*lane..8*lane+7)
        unsigned long long acc[8][4];
        #pragma unroll
        for (int j = 0; j < 8; j++)
            #pragma unroll
            for (int p = 0; p < 4; p++) acc[j][p] = 0ull;

        #pragma unroll 2
        for (int c = 0; c < 64; c++) {
            const ulonglong2 ca = *(const ulonglong2*)&s_tile[c * 260 + 8 * lane];
            const ulonglong2 cb = *(const ulonglong2*)&s_tile[c * 260 + 8 * lane + 4];
            #pragma unroll
            for (int j = 0; j < 8; j++) {
                unsigned long long rv = *(const unsigned long long*)&s_row2[(8 * w + j) * 65 + c];
                fma2(acc[j][0], rv, ca.x);
                fma2(acc[j][1], rv, ca.y);
                fma2(acc[j][2], rv, cb.x);
                fma2(acc[j][3], rv, cb.y);
            }
        }

        // selection
        float ntx[8];
        {
            float4 n0 = *(const float4*)&s_ntxx[8 * lane];
            float4 n1 = *(const float4*)&s_ntxx[8 * lane + 4];
            ntx[0] = n0.x; ntx[1] = n0.y; ntx[2] = n0.z; ntx[3] = n0.w;
            ntx[4] = n1.x; ntx[5] = n1.y; ntx[6] = n1.z; ntx[7] = n1.w;
        }
        #pragma unroll
        for (int j = 0; j < 8; j++) {
            float pd[8];
            #pragma unroll
            for (int p = 0; p < 4; p++) {
                float a0, a1;
                upk2(a0, a1, acc[j][p]);
                pd[2 * p]     = a0 + ntx[2 * p];
                pd[2 * p + 1] = a1 + ntx[2 * p + 1];
            }
            float lmax = pd[0];
            #pragma unroll
            for (int q = 1; q < 8; q++) lmax = fmaxf(lmax, pd[q]);

            unsigned act = __ballot_sync(0xffffffffu, lmax > rmin[j]);
            while (act) {
                int src = __ffs(act) - 1; act &= act - 1;
                #pragma unroll
                for (int q = 0; q < 8; q++) {
                    float v = __shfl_sync(0xffffffffu, pd[q], src);
                    if (v > rmin[j]) {                 // uniform branch
                        unsigned eq = __ballot_sync(0xffffffffu, val[j] == rmin[j]);
                        int sel = __ffs(eq) - 1;
                        if (lane == sel) { val[j] = v; idxr[j] = m0 + 8 * src + q; }
                        float mv = val[j];
                        #pragma unroll
                        for (int off = 16; off > 0; off >>= 1)
                            mv = fminf(mv, __shfl_xor_sync(0xffffffffu, mv, off));
                        rmin[j] = mv;
                    }
                }
            }
        }
    }

    if (lane < KK) {
        #pragma unroll
        for (int j = 0; j < 8; j++)
            g_idx[((size_t)b * NN + r0 + 8 * w + j) * KK + lane] = idxr[j];
    }
}

// ============================================================================
// K3: per-point gated MLP, FFMA2 throughout. Warp per point, 148 CTAs.
// softmax over k sums to 1 => center half of gated feats = x_n exactly;
// only h[:, d<64] needed. Gates packed per-lane as (d=2l, d=2l+1).
// dyn smem (floats):
//   sW1h  [128][68]        @0       sW1h[cin][d], d<64
//   sW2   [128][132]       @8704    sW2[c][o]
//   sdiffd(f2)[8][20][64]  @25600   (d,d) duplicated pairs
//   sxnd  (f2)[8][64]      @46080   (xn,xn)
//   sgd   (f2)[8][128]     @47104   (g,g)      total 49152 f = 192 KB
// ============================================================================
#define MLP_SMEM (49152 * 4)

__global__ __launch_bounds__(256) void k_mlp(const float* __restrict__ W1,
                                             const float* __restrict__ W2,
                                             float* __restrict__ out) {
    extern __shared__ float sm[];
    float*  sW1h   = sm;                       // [cin*68 + d]
    float*  sW2    = sm + 8704;                // [c*132 + o]
    float2* sdiffd = (float2*)(sm + 25600);    // [(wid*20+k)*64 + c]
    float2* sxnd   = (float2*)(sm + 46080);    // [wid*64 + c]
    float2* sgd    = (float2*)(sm + 47104);    // [wid*128 + c]

    int tid = threadIdx.x, lane = tid & 31, wid = tid >> 5;

    for (int i = tid; i < 64 * 128; i += 256) {
        int d = i >> 7, c = i & 127;
        sW1h[c * 68 + d] = W1[i];
    }
    for (int i = tid; i < 128 * 128; i += 256) {
        int o = i >> 7, c = i & 127;
        sW2[c * 132 + o] = W2[i];
    }
    __syncthreads();

    float2* dif2 = sdiffd + wid * 20 * 64;

    int gw = blockIdx.x * 8 + wid;
    for (int p = gw; p < NB * NN; p += 148 * 8) {
        int b = p >> 13, n = p & (NN - 1);
        const float* xc = g_xt + (size_t)p * 64;
        float xn0 = xc[lane], xn1 = xc[lane + 32];
        sxnd[wid * 64 + lane]      = make_float2(xn0, xn0);
        sxnd[wid * 64 + lane + 32] = make_float2(xn1, xn1);

        int midx = 0;
        if (lane < KK) midx = g_idx[p * KK + lane];
        #pragma unroll
        for (int k = 0; k < KK; k++) {
            int m = __shfl_sync(0xffffffffu, midx, k);
            const float* xm = g_xt + ((size_t)b * NN + m) * 64;
            float d0 = xm[lane]      - xn0;
            float d1 = xm[lane + 32] - xn1;
            dif2[k * 64 + lane]      = make_float2(d0, d0);
            dif2[k * 64 + lane + 32] = make_float2(d1, d1);
        }
        __syncwarp();

        // h for d = (2l, 2l+1) packed; FFMA2 over c
        unsigned long long h01[KK];
        #pragma unroll
        for (int k = 0; k < KK; k++) h01[k] = 0ull;
        unsigned long long hc = 0ull;
        #pragma unroll 2
        for (int c = 0; c < 64; c++) {
            unsigned long long wa  = *(const unsigned long long*)&sW1h[c * 68 + 2 * lane];
            unsigned long long wb  = *(const unsigned long long*)&sW1h[(64 + c) * 68 + 2 * lane];
            unsigned long long xc2 = *(const unsigned long long*)&sxnd[wid * 64 + c];
            fma2(hc, xc2, wb);
            #pragma unroll
            for (int k = 0; k < KK; k++) {
                unsigned long long dd = *(const unsigned long long*)&dif2[k * 64 + c];
                fma2(h01[k], dd, wa);
            }
        }
        // softmax over k (two d-columns per lane)
        float hcx, hcy;
        upk2(hcx, hcy, hc);
        float h0[KK], h1[KK];
        float m0v = -INFINITY, m1v = -INFINITY;
        #pragma unroll
        for (int k = 0; k < KK; k++) {
            upk2(h0[k], h1[k], h01[k]);
            h0[k] += hcx; h1[k] += hcy;
            m0v = fmaxf(m0v, h0[k]); m1v = fmaxf(m1v, h1[k]);
        }
        float s0 = 0.f, s1 = 0.f;
        #pragma unroll
        for (int k = 0; k < KK; k++) {
            h0[k] = __expf(h0[k] - m0v); s0 += h0[k];
            h1[k] = __expf(h1[k] - m1v); s1 += h1[k];
        }
        float i0 = 1.f / s0, i1 = 1.f / s1;

        // gA for c = (2l, 2l+1)
        unsigned long long ga2 = 0ull;
        #pragma unroll
        for (int k = 0; k < KK; k++) {
            ulonglong2 dp = *(const ulonglong2*)&dif2[k * 64 + 2 * lane];
            float d0, d1, t;
            upk2(d0, t, dp.x);
            upk2(d1, t, dp.y);
            fma2(ga2, pk2(d0, d1), pk2(h0[k], h1[k]));
        }
        ga2 = mul2(ga2, pk2(i0, i1));
        float ga0, ga1;
        upk2(ga0, ga1, ga2);

        sgd[wid * 128 + 2 * lane]     = make_float2(ga0, ga0);
        sgd[wid * 128 + 2 * lane + 1] = make_float2(ga1, ga1);
        sgd[wid * 128 + 64 + lane]    = make_float2(xn0, xn0);  // center half
        sgd[wid * 128 + 96 + lane]    = make_float2(xn1, xn1);
        __syncwarp();

        // out[o] = sum_c W2[o][c] * g[c] ; lane owns o = 4*lane..+3
        unsigned long long o01 = 0ull, o23 = 0ull;
        const float2* gpd = sgd + wid * 128;
        #pragma unroll 4
        for (int c = 0; c < 128; c++) {
            unsigned long long gv = *(const unsigned long long*)&gpd[c];
            ulonglong2 wp = *(const ulonglong2*)&sW2[c * 132 + 4 * lane];
            fma2(o01, gv, wp.x);
            fma2(o23, gv, wp.y);
        }
        float o0, o1, o2, o3;
        upk2(o0, o1, o01);
        upk2(o2, o3, o23);
        float* op = out + (size_t)b * NO * NN + n;
        op[(4 * lane + 0) * NN] = o0;
        op[(4 * lane + 1) * NN] = o1;
        op[(4 * lane + 2) * NN] = o2;
        op[(4 * lane + 3) * NN] = o3;
        __syncwarp();
    }
}

// ============================================================================
extern "C" void kernel_launch(void* const* d_in, const int* in_sizes, int n_in,
                              void* d_out, int out_size) {
    const float* x  = (const float*)d_in[0];
    const float* W1 = (const float*)d_in[1];
    const float* W2 = (const float*)d_in[2];
    float* out = (float*)d_out;

    cudaFuncSetAttribute(k_knn, cudaFuncAttributeMaxDynamicSharedMemorySize, KNN_SMEM);
    cudaFuncSetAttribute(k_mlp, cudaFuncAttributeMaxDynamicSharedMemorySize, MLP_SMEM);

    dim3 g1(NN / 64, NB);
    k_prep<<<g1, 256>>>(x);
    dim3 g2(NN / 64, NB);
    k_knn<<<g2, 256, KNN_SMEM>>>(x);
    k_mlp<<<148, 256, MLP_SMEM>>>(W1, W2, out);
}